// round 12
// baseline (speedup 1.0000x reference)
#include <cuda_runtime.h>
#include <cstdint>

#define NUM_JOINT 19
#define ROOT_SCALE 200.0f
#define BLOCK 32
#define EPT 64                                 // elements per tile (2 per thread)
#define TILE_FLOATS (EPT * NUM_JOINT * 4)      // 4864
#define TILE_BYTES  (TILE_FLOATS * 4)          // 19456
#define NCTA_SM 5
#define GRID (148 * NCTA_SM)                   // 740 persistent CTAs

__constant__ float c_off[NUM_JOINT * 16];

// ---- packed f32x2 helpers (sm_100+ dual-lane float ops) ----
typedef unsigned long long f2;
__device__ __forceinline__ f2 pk(float lo, float hi) {
    f2 r; asm("mov.b64 %0,{%1,%2};" : "=l"(r) : "f"(lo), "f"(hi)); return r;
}
__device__ __forceinline__ f2 pk1(float v) {
    f2 r; asm("mov.b64 %0,{%1,%1};" : "=l"(r) : "f"(v)); return r;
}
__device__ __forceinline__ void upk(f2 v, float& lo, float& hi) {
    asm("mov.b64 {%0,%1},%2;" : "=f"(lo), "=f"(hi) : "l"(v));
}
__device__ __forceinline__ f2 f2mul(f2 a, f2 b) {
    f2 r; asm("mul.rn.f32x2 %0,%1,%2;" : "=l"(r) : "l"(a), "l"(b)); return r;
}
__device__ __forceinline__ f2 f2add(f2 a, f2 b) {
    f2 r; asm("add.rn.f32x2 %0,%1,%2;" : "=l"(r) : "l"(a), "l"(b)); return r;
}
__device__ __forceinline__ f2 f2fma(f2 a, f2 b, f2 c) {
    f2 r; asm("fma.rn.f32x2 %0,%1,%2,%3;" : "=l"(r) : "l"(a), "l"(b), "l"(c)); return r;
}
__device__ __forceinline__ f2 f2neg(f2 a) {   // sign-flip both lanes (ALU pipe)
    f2 r; asm("xor.b64 %0,%1,0x8000000080000000;" : "=l"(r) : "l"(a)); return r;
}
__device__ __forceinline__ f2 f2rcp(f2 n) {
    float a, b, ra, rb; upk(n, a, b);
    asm("rcp.approx.f32 %0,%1;" : "=f"(ra) : "f"(a));
    asm("rcp.approx.f32 %0,%1;" : "=f"(rb) : "f"(b));
    return pk(ra, rb);
}

__device__ __forceinline__ void tma_load(uint32_t sdst, const float* gsrc, uint32_t mb) {
    asm volatile("mbarrier.arrive.expect_tx.shared.b64 _, [%0], %1;"
                 :: "r"(mb), "r"((uint32_t)TILE_BYTES) : "memory");
    asm volatile("cp.async.bulk.shared::cta.global.mbarrier::complete_tx::bytes "
                 "[%0], [%1], %2, [%3];"
                 :: "r"(sdst), "l"(gsrc), "r"((uint32_t)TILE_BYTES), "r"(mb) : "memory");
}

__global__ __launch_bounds__(BLOCK, NCTA_SM)
void fk_kernel(const float* __restrict__ root,
               const float* __restrict__ joint,
               float* __restrict__ out,
               int ntiles)
{
    __shared__ alignas(16) float s[2][TILE_FLOATS];        // 38912 B
    __shared__ alignas(8)  unsigned long long mbar[2];

    const int t = threadIdx.x;
    const uint32_t s0 = (uint32_t)__cvta_generic_to_shared(&s[0][0]);
    const uint32_t m0 = (uint32_t)__cvta_generic_to_shared(&mbar[0]);

    if (t == 0) {
        asm volatile("mbarrier.init.shared.b64 [%0], 1;" :: "r"(m0)     : "memory");
        asm volatile("mbarrier.init.shared.b64 [%0], 1;" :: "r"(m0 + 8) : "memory");
    }
    __syncwarp();

    const int parents[NUM_JOINT] = {-1,0,1,2,3,2,5,6,7,2,9,10,11,0,13,14,0,16,17};

    if (t == 0 && blockIdx.x < ntiles)
        tma_load(s0, joint + (size_t)blockIdx.x * TILE_FLOATS, m0);

    int it = 0;
    for (int tile = blockIdx.x; tile < ntiles; tile += GRID, it++) {
        const int buf = it & 1;
        const uint32_t parity = (uint32_t)((it >> 1) & 1);
        const uint32_t sbuf = s0 + buf * TILE_BYTES;

        // Packed roots for elements (lane, lane+32); overlaps the load wait.
        const long long e0 = (long long)tile * EPT + t;
        const long long e1 = e0 + 32;
        const f2 rx2 = pk(__ldg(&root[e0*3+0]) * ROOT_SCALE, __ldg(&root[e1*3+0]) * ROOT_SCALE);
        const f2 ry2 = pk(__ldg(&root[e0*3+1]) * ROOT_SCALE, __ldg(&root[e1*3+1]) * ROOT_SCALE);
        const f2 rz2 = pk(__ldg(&root[e0*3+2]) * ROOT_SCALE, __ldg(&root[e1*3+2]) * ROOT_SCALE);

        asm volatile(
            "{\n\t.reg .pred P;\n\t"
            "W%=:\n\t"
            "mbarrier.try_wait.parity.acquire.cta.shared::cta.b64 P, [%0], %1, 0x989680;\n\t"
            "@!P bra W%=;\n\t}"
            :: "r"(m0 + buf * 8), "r"(parity) : "memory");

        // Prefetch next tile into the other buffer; drain its pending store first.
        if (t == 0 && tile + GRID < ntiles) {
            asm volatile("cp.async.bulk.wait_group 0;" ::: "memory");
            tma_load(s0 + (buf ^ 1) * TILE_BYTES,
                     joint + (size_t)(tile + GRID) * TILE_FLOATS, m0 + (buf ^ 1) * 8);
        }

        float* rowA = &s[buf][ t       * (NUM_JOINT * 4)];  // 76-float stride: conflict-free
        float* rowB = &s[buf][(t + 32) * (NUM_JOINT * 4)];

        // Packed FK chain; only branch-point state stays live (compiler prunes).
        f2 gw[NUM_JOINT], gx[NUM_JOINT], gy[NUM_JOINT], gz[NUM_JOINT];
        f2 ox[NUM_JOINT], oy[NUM_JOINT], oz[NUM_JOINT];

        #pragma unroll
        for (int j = 0; j < NUM_JOINT; j++) {
            const float4 qa = *(const float4*)&rowA[j * 4];
            const float4 qb = *(const float4*)&rowB[j * 4];
            const f2 bw = pk(qa.x, qb.x), bx = pk(qa.y, qb.y);
            const f2 by = pk(qa.z, qb.z), bz = pk(qa.w, qb.w);

            f2 aw, ax, ay, az;
            if (j == 0) {
                aw = bw; ax = bx; ay = by; az = bz;
            } else {
                const int p = parents[j];
                aw = f2fma(gw[p],bw, f2neg(f2fma(gx[p],bx, f2fma(gy[p],by, f2mul(gz[p],bz)))));
                ax = f2fma(gw[p],bx, f2fma(gx[p],bw, f2fma(gy[p],bz, f2neg(f2mul(gz[p],by)))));
                ay = f2fma(gw[p],by, f2fma(gy[p],bw, f2fma(gz[p],bx, f2neg(f2mul(gx[p],bz)))));
                az = f2fma(gw[p],bz, f2fma(gz[p],bw, f2fma(gx[p],by, f2neg(f2mul(gy[p],bx)))));
            }
            gw[j] = aw; gx[j] = ax; gy[j] = ay; gz[j] = az;

            // o = t + (2/|g|^2)*(aw*c + g x c),  c = g x t
            const f2 tx2 = pk1(c_off[j * 16 + 3]);
            const f2 ty2 = pk1(c_off[j * 16 + 7]);
            const f2 tz2 = pk1(c_off[j * 16 + 11]);

            const f2 n = f2fma(aw,aw, f2fma(ax,ax, f2fma(ay,ay, f2mul(az,az))));
            const f2 r = f2rcp(n);

            const f2 cx = f2fma(ay,tz2, f2neg(f2mul(az,ty2)));
            const f2 cy = f2fma(az,tx2, f2neg(f2mul(ax,tz2)));
            const f2 cz = f2fma(ax,ty2, f2neg(f2mul(ay,tx2)));

            const f2 dx = f2fma(aw,cx, f2fma(ay,cz, f2neg(f2mul(az,cy))));
            const f2 dy = f2fma(aw,cy, f2fma(az,cx, f2neg(f2mul(ax,cz))));
            const f2 dz = f2fma(aw,cz, f2fma(ax,cy, f2neg(f2mul(ay,cx))));

            // double d, multiply by rcp(n): t + 2*d/n
            f2 vx = f2fma(f2add(dx,dx), r, tx2);
            f2 vy = f2fma(f2add(dy,dy), r, ty2);
            f2 vz = f2fma(f2add(dz,dz), r, tz2);
            if (j > 0) {
                const int p = parents[j];
                vx = f2add(vx, ox[p]); vy = f2add(vy, oy[p]); vz = f2add(vz, oz[p]);
            }
            ox[j] = vx; oy[j] = vy; oz[j] = vz;

            // Final (+root), unpack, in-place STS over quat j.
            const f2 fx = f2add(vx, rx2), fy = f2add(vy, ry2), fz = f2add(vz, rz2);
            float fxa, fxb, fya, fyb, fza, fzb;
            upk(fx, fxa, fxb); upk(fy, fya, fyb); upk(fz, fza, fzb);
            *(float4*)&rowA[j * 4] = make_float4(fxa, fya, fza, 1.0f);
            *(float4*)&rowB[j * 4] = make_float4(fxb, fyb, fzb, 1.0f);
        }
        __syncwarp();

        if (t == 0) {
            asm volatile("fence.proxy.async.shared::cta;" ::: "memory");
            float* gdst = out + (size_t)tile * TILE_FLOATS;
            asm volatile("cp.async.bulk.global.shared::cta.bulk_group [%0], [%1], %2;"
                         :: "l"(gdst), "r"(sbuf), "r"((uint32_t)TILE_BYTES) : "memory");
            asm volatile("cp.async.bulk.commit_group;" ::: "memory");
        }
    }

    if (t == 0)
        asm volatile("cp.async.bulk.wait_group 0;" ::: "memory");
}

extern "C" void kernel_launch(void* const* d_in, const int* in_sizes, int n_in,
                              void* d_out, int out_size)
{
    const float* root    = (const float*)d_in[0];   // (B, 3)
    const float* joint   = (const float*)d_in[1];   // (B, 76)
    const float* offsets = (const float*)d_in[2];   // (19, 4, 4)
    float* out = (float*)d_out;                     // (B, 19, 4)

    cudaMemcpyToSymbolAsync(c_off, offsets, NUM_JOINT * 16 * sizeof(float),
                            0, cudaMemcpyDeviceToDevice, 0);

    const int B = in_sizes[1] / (NUM_JOINT * 4);    // 262144
    const int ntiles = B / EPT;                     // 4096
    fk_kernel<<<GRID, BLOCK>>>(root, joint, out, ntiles);
}

// round 13
// speedup vs baseline: 1.1979x; 1.1979x over previous
#include <cuda_runtime.h>
#include <cstdint>

#define NUM_JOINT 19
#define ROOT_SCALE 200.0f
#define BLOCK 32
#define TILE_FLOATS (BLOCK * NUM_JOINT * 4)   // 2432
#define TILE_BYTES  (TILE_FLOATS * 4)         // 9728
#define GRID 1024                              // 8192 tiles = exactly 8 per CTA

__device__ __forceinline__ void tma_load(uint32_t sdst, const float* gsrc, uint32_t mb) {
    asm volatile("mbarrier.arrive.expect_tx.shared.b64 _, [%0], %1;"
                 :: "r"(mb), "r"((uint32_t)TILE_BYTES) : "memory");
    asm volatile("cp.async.bulk.shared::cta.global.mbarrier::complete_tx::bytes "
                 "[%0], [%1], %2, [%3];"
                 :: "r"(sdst), "l"(gsrc), "r"((uint32_t)TILE_BYTES), "r"(mb) : "memory");
}

__global__ __launch_bounds__(BLOCK, 7)
void fk_kernel(const float* __restrict__ root,
               const float* __restrict__ joint,
               const float* __restrict__ offsets,
               float* __restrict__ out,
               int ntiles)
{
    __shared__ alignas(16) float s[3][TILE_FLOATS];        // 29184 B rotating ring
    __shared__ alignas(8)  unsigned long long mbar[3];

    const int t = threadIdx.x;
    const uint32_t s0 = (uint32_t)__cvta_generic_to_shared(&s[0][0]);
    const uint32_t m0 = (uint32_t)__cvta_generic_to_shared(&mbar[0]);

    if (t == 0) {
        #pragma unroll
        for (int k = 0; k < 3; k++)
            asm volatile("mbarrier.init.shared.b64 [%0], 1;" :: "r"(m0 + k * 8) : "memory");
    }
    __syncwarp();

    const int parents[NUM_JOINT] = {-1,0,1,2,3,2,5,6,7,2,9,10,11,0,13,14,0,16,17};

    // Translations -> registers once per persistent CTA (uniform LDG broadcast;
    // replaces the per-replay memcpyToSymbol graph node).
    float tox[NUM_JOINT], toy[NUM_JOINT], toz[NUM_JOINT];
    #pragma unroll
    for (int j = 0; j < NUM_JOINT; j++) {
        tox[j] = __ldg(&offsets[j * 16 + 3]);
        toy[j] = __ldg(&offsets[j * 16 + 7]);
        toz[j] = __ldg(&offsets[j * 16 + 11]);
    }

    // Prologue: depth-2 prefetch of tiles it=0,1 into bufs 0,1.
    if (t == 0) {
        if (blockIdx.x < ntiles)
            tma_load(s0, joint + (size_t)blockIdx.x * TILE_FLOATS, m0);
        if (blockIdx.x + GRID < ntiles)
            tma_load(s0 + TILE_BYTES,
                     joint + (size_t)(blockIdx.x + GRID) * TILE_FLOATS, m0 + 8);
    }

    int it = 0;
    for (int tile = blockIdx.x; tile < ntiles; tile += GRID, it++) {
        const int buf = it % 3;
        const uint32_t parity = (uint32_t)((it / 3) & 1);
        const uint32_t sbuf = s0 + buf * TILE_BYTES;

        // Root fetch overlaps the load-wait window.
        const long long b = (long long)tile * BLOCK + t;
        const float rx = __ldg(&root[b * 3 + 0]) * ROOT_SCALE;
        const float ry = __ldg(&root[b * 3 + 1]) * ROOT_SCALE;
        const float rz = __ldg(&root[b * 3 + 2]) * ROOT_SCALE;

        // Wait for this tile (its load was issued two iterations ago).
        asm volatile(
            "{\n\t.reg .pred P;\n\t"
            "W%=:\n\t"
            "mbarrier.try_wait.parity.acquire.cta.shared::cta.b64 P, [%0], %1, 0x989680;\n\t"
            "@!P bra W%=;\n\t}"
            :: "r"(m0 + buf * 8), "r"(parity) : "memory");

        // Slurp all 19 quats into registers; frees buf for the result writes.
        const float* row = &s[buf][t * (NUM_JOINT * 4)];   // 76-float stride: conflict-free
        float4 q[NUM_JOINT];
        #pragma unroll
        for (int j = 0; j < NUM_JOINT; j++)
            q[j] = *(const float4*)&row[j * 4];
        __syncwarp();

        // Depth-2 prefetch: tile it+2 -> buf (it+2)%3. Drain that buffer's
        // pending store (tile it-1, committed last iteration) first.
        if (t == 0 && tile + 2 * GRID < ntiles) {
            asm volatile("cp.async.bulk.wait_group 0;" ::: "memory");
            const int nb = (it + 2) % 3;
            tma_load(s0 + nb * TILE_BYTES,
                     joint + (size_t)(tile + 2 * GRID) * TILE_FLOATS, m0 + nb * 8);
        }

        // ---- FK chain via composite (non-unit) quaternions, in registers ----
        float gw[NUM_JOINT], gx[NUM_JOINT], gy[NUM_JOINT], gz[NUM_JOINT];
        float ox[NUM_JOINT], oy[NUM_JOINT], oz[NUM_JOINT];
        #pragma unroll
        for (int j = 0; j < NUM_JOINT; j++) {
            float aw, ax, ay, az;
            if (j == 0) {
                aw = q[0].x; ax = q[0].y; ay = q[0].z; az = q[0].w;
            } else {
                const int p = parents[j];
                const float bw = q[j].x, bx = q[j].y, by = q[j].z, bz = q[j].w;
                aw = gw[p]*bw - gx[p]*bx - gy[p]*by - gz[p]*bz;
                ax = gw[p]*bx + gx[p]*bw + gy[p]*bz - gz[p]*by;
                ay = gw[p]*by - gx[p]*bz + gy[p]*bw + gz[p]*bx;
                az = gw[p]*bz + gx[p]*by - gy[p]*bx + gz[p]*bw;
            }
            gw[j] = aw; gx[j] = ax; gy[j] = ay; gz[j] = az;

            const float tx = tox[j], ty = toy[j], tz = toz[j];

            const float n  = aw*aw + ax*ax + ay*ay + az*az;
            const float sc = __fdividef(2.0f, n);

            const float cx = ay*tz - az*ty;
            const float cy = az*tx - ax*tz;
            const float cz = ax*ty - ay*tx;

            const float dx = aw*cx + (ay*cz - az*cy);
            const float dy = aw*cy + (az*cx - ax*cz);
            const float dz = aw*cz + (ax*cy - ay*cx);

            float vx = tx + sc * dx;
            float vy = ty + sc * dy;
            float vz = tz + sc * dz;
            if (j > 0) {
                const int p = parents[j];
                vx += ox[p]; vy += oy[p]; vz += oz[p];
            }
            ox[j] = vx; oy[j] = vy; oz[j] = vz;
        }

        // Results overwrite this tile's buffer; its next TMA load happens only
        // after the wait_group above drains this store next iteration.
        float* wrow = &s[buf][t * (NUM_JOINT * 4)];
        #pragma unroll
        for (int j = 0; j < NUM_JOINT; j++) {
            float4 o;
            o.x = ox[j] + rx; o.y = oy[j] + ry; o.z = oz[j] + rz; o.w = 1.0f;
            *(float4*)&wrow[j * 4] = o;
        }
        __syncwarp();

        if (t == 0) {
            asm volatile("fence.proxy.async.shared::cta;" ::: "memory");
            float* gdst = out + (size_t)tile * TILE_FLOATS;
            asm volatile("cp.async.bulk.global.shared::cta.bulk_group [%0], [%1], %2;"
                         :: "l"(gdst), "r"(sbuf), "r"((uint32_t)TILE_BYTES) : "memory");
            asm volatile("cp.async.bulk.commit_group;" ::: "memory");
        }
    }

    // smem must outlive the final store.
    if (t == 0)
        asm volatile("cp.async.bulk.wait_group 0;" ::: "memory");
}

extern "C" void kernel_launch(void* const* d_in, const int* in_sizes, int n_in,
                              void* d_out, int out_size)
{
    const float* root    = (const float*)d_in[0];   // (B, 3)
    const float* joint   = (const float*)d_in[1];   // (B, 76)
    const float* offsets = (const float*)d_in[2];   // (19, 4, 4)
    float* out = (float*)d_out;                     // (B, 19, 4)

    const int B = in_sizes[1] / (NUM_JOINT * 4);    // 262144
    const int ntiles = B / BLOCK;                   // 8192
    fk_kernel<<<GRID, BLOCK>>>(root, joint, offsets, out, ntiles);
}

// round 14
// speedup vs baseline: 1.2129x; 1.0125x over previous
#include <cuda_runtime.h>
#include <cstdint>

#define NUM_JOINT 19
#define ROOT_SCALE 200.0f
#define BLOCK 32
#define TILE_FLOATS (BLOCK * NUM_JOINT * 4)   // 2432
#define TILE_BYTES  (TILE_FLOATS * 4)         // 9728
#define GRID (148 * 7)                         // 1036: every SM exactly 7 CTAs

__device__ __forceinline__ void tma_load(uint32_t sdst, const float* gsrc, uint32_t mb) {
    asm volatile("mbarrier.arrive.expect_tx.shared.b64 _, [%0], %1;"
                 :: "r"(mb), "r"((uint32_t)TILE_BYTES) : "memory");
    asm volatile("cp.async.bulk.shared::cta.global.mbarrier::complete_tx::bytes "
                 "[%0], [%1], %2, [%3];"
                 :: "r"(sdst), "l"(gsrc), "r"((uint32_t)TILE_BYTES), "r"(mb) : "memory");
}

__global__ __launch_bounds__(BLOCK, 7)
void fk_kernel(const float* __restrict__ root,
               const float* __restrict__ joint,
               const float* __restrict__ offsets,
               float* __restrict__ out,
               int ntiles)
{
    __shared__ alignas(16) float s[3][TILE_FLOATS];        // 29184 B rotating ring
    __shared__ alignas(8)  unsigned long long mbar[3];

    const int t = threadIdx.x;
    const uint32_t s0 = (uint32_t)__cvta_generic_to_shared(&s[0][0]);
    const uint32_t m0 = (uint32_t)__cvta_generic_to_shared(&mbar[0]);

    if (t == 0) {
        #pragma unroll
        for (int k = 0; k < 3; k++)
            asm volatile("mbarrier.init.shared.b64 [%0], 1;" :: "r"(m0 + k * 8) : "memory");
    }
    __syncwarp();

    const int parents[NUM_JOINT] = {-1,0,1,2,3,2,5,6,7,2,9,10,11,0,13,14,0,16,17};

    // Translations -> registers once per persistent CTA (uniform LDG broadcast).
    float tox[NUM_JOINT], toy[NUM_JOINT], toz[NUM_JOINT];
    #pragma unroll
    for (int j = 0; j < NUM_JOINT; j++) {
        tox[j] = __ldg(&offsets[j * 16 + 3]);
        toy[j] = __ldg(&offsets[j * 16 + 7]);
        toz[j] = __ldg(&offsets[j * 16 + 11]);
    }

    // Prologue: depth-2 prefetch of tiles it=0,1 into bufs 0,1.
    if (t == 0) {
        if (blockIdx.x < ntiles)
            tma_load(s0, joint + (size_t)blockIdx.x * TILE_FLOATS, m0);
        if (blockIdx.x + GRID < ntiles)
            tma_load(s0 + TILE_BYTES,
                     joint + (size_t)(blockIdx.x + GRID) * TILE_FLOATS, m0 + 8);
    }

    int it = 0;
    for (int tile = blockIdx.x; tile < ntiles; tile += GRID, it++) {
        const int buf = it % 3;
        const uint32_t parity = (uint32_t)((it / 3) & 1);
        const uint32_t sbuf = s0 + buf * TILE_BYTES;

        // Root fetch overlaps the load-wait window.
        const long long b = (long long)tile * BLOCK + t;
        const float rx = __ldg(&root[b * 3 + 0]) * ROOT_SCALE;
        const float ry = __ldg(&root[b * 3 + 1]) * ROOT_SCALE;
        const float rz = __ldg(&root[b * 3 + 2]) * ROOT_SCALE;

        // Wait for this tile (its load was issued two iterations ago).
        asm volatile(
            "{\n\t.reg .pred P;\n\t"
            "W%=:\n\t"
            "mbarrier.try_wait.parity.acquire.cta.shared::cta.b64 P, [%0], %1, 0x989680;\n\t"
            "@!P bra W%=;\n\t}"
            :: "r"(m0 + buf * 8), "r"(parity) : "memory");

        // Slurp all 19 quats into registers; frees buf for the result writes.
        const float* row = &s[buf][t * (NUM_JOINT * 4)];   // 76-float stride: conflict-free
        float4 q[NUM_JOINT];
        #pragma unroll
        for (int j = 0; j < NUM_JOINT; j++)
            q[j] = *(const float4*)&row[j * 4];
        __syncwarp();

        // Depth-2 prefetch: tile it+2 -> buf (it+2)%3. Drain that buffer's
        // pending store (tile it-1, committed last iteration) first.
        if (t == 0 && tile + 2 * GRID < ntiles) {
            asm volatile("cp.async.bulk.wait_group 0;" ::: "memory");
            const int nb = (it + 2) % 3;
            tma_load(s0 + nb * TILE_BYTES,
                     joint + (size_t)(tile + 2 * GRID) * TILE_FLOATS, m0 + nb * 8);
        }

        // ---- FK chain via composite (non-unit) quaternions, in registers ----
        float gw[NUM_JOINT], gx[NUM_JOINT], gy[NUM_JOINT], gz[NUM_JOINT];
        float ox[NUM_JOINT], oy[NUM_JOINT], oz[NUM_JOINT];
        #pragma unroll
        for (int j = 0; j < NUM_JOINT; j++) {
            float aw, ax, ay, az;
            if (j == 0) {
                aw = q[0].x; ax = q[0].y; ay = q[0].z; az = q[0].w;
            } else {
                const int p = parents[j];
                const float bw = q[j].x, bx = q[j].y, by = q[j].z, bz = q[j].w;
                aw = gw[p]*bw - gx[p]*bx - gy[p]*by - gz[p]*bz;
                ax = gw[p]*bx + gx[p]*bw + gy[p]*bz - gz[p]*by;
                ay = gw[p]*by - gx[p]*bz + gy[p]*bw + gz[p]*bx;
                az = gw[p]*bz + gx[p]*by - gy[p]*bx + gz[p]*bw;
            }
            gw[j] = aw; gx[j] = ax; gy[j] = ay; gz[j] = az;

            const float tx = tox[j], ty = toy[j], tz = toz[j];

            const float n  = aw*aw + ax*ax + ay*ay + az*az;
            const float sc = __fdividef(2.0f, n);

            const float cx = ay*tz - az*ty;
            const float cy = az*tx - ax*tz;
            const float cz = ax*ty - ay*tx;

            const float dx = aw*cx + (ay*cz - az*cy);
            const float dy = aw*cy + (az*cx - ax*cz);
            const float dz = aw*cz + (ax*cy - ay*cx);

            float vx = tx + sc * dx;
            float vy = ty + sc * dy;
            float vz = tz + sc * dz;
            if (j > 0) {
                const int p = parents[j];
                vx += ox[p]; vy += oy[p]; vz += oz[p];
            }
            ox[j] = vx; oy[j] = vy; oz[j] = vz;
        }

        // Results overwrite this tile's buffer; its next TMA load happens only
        // after the wait_group above drains this store next iteration.
        float* wrow = &s[buf][t * (NUM_JOINT * 4)];
        #pragma unroll
        for (int j = 0; j < NUM_JOINT; j++) {
            float4 o;
            o.x = ox[j] + rx; o.y = oy[j] + ry; o.z = oz[j] + rz; o.w = 1.0f;
            *(float4*)&wrow[j * 4] = o;
        }
        __syncwarp();

        if (t == 0) {
            asm volatile("fence.proxy.async.shared::cta;" ::: "memory");
            float* gdst = out + (size_t)tile * TILE_FLOATS;
            asm volatile("cp.async.bulk.global.shared::cta.bulk_group [%0], [%1], %2;"
                         :: "l"(gdst), "r"(sbuf), "r"((uint32_t)TILE_BYTES) : "memory");
            asm volatile("cp.async.bulk.commit_group;" ::: "memory");
        }
    }

    // smem must outlive the final store.
    if (t == 0)
        asm volatile("cp.async.bulk.wait_group 0;" ::: "memory");
}

extern "C" void kernel_launch(void* const* d_in, const int* in_sizes, int n_in,
                              void* d_out, int out_size)
{
    const float* root    = (const float*)d_in[0];   // (B, 3)
    const float* joint   = (const float*)d_in[1];   // (B, 76)
    const float* offsets = (const float*)d_in[2];   // (19, 4, 4)
    float* out = (float*)d_out;                     // (B, 19, 4)

    const int B = in_sizes[1] / (NUM_JOINT * 4);    // 262144
    const int ntiles = B / BLOCK;                   // 8192
    fk_kernel<<<GRID, BLOCK>>>(root, joint, offsets, out, ntiles);
}